// round 2
// baseline (speedup 1.0000x reference)
#include <cuda_runtime.h>
#include <math.h>

#define TPB 256
#define SEQL 3072
#define DMODEL 1024
#define NHEAD 16
#define DHEAD 64
#define SPRIME 768      // SEQL / 4 (dilation)
#define KTILE 192       // 127 + 64 key rows per attention tile
#define QTILE 64

// ---------------- scratch (device globals; no allocation allowed) -------------
__device__ __align__(16) float g_q[NHEAD * 4 * SPRIME * DHEAD];
__device__ __align__(16) float g_k[NHEAD * 4 * SPRIME * DHEAD];
__device__ __align__(16) float g_v[NHEAD * 4 * SPRIME * DHEAD];
__device__ __align__(16) float g_ctx[SEQL * DMODEL];

// ---------------- tf32 helpers -----------------------------------------------
__device__ __forceinline__ unsigned f2tf(float f) {
    unsigned u;
    asm("cvt.rna.tf32.f32 %0, %1;" : "=r"(u) : "f"(f));
    return u;
}

__device__ __forceinline__ void mma8(float* c, const unsigned* a, const unsigned* b) {
    asm volatile(
        "mma.sync.aligned.m16n8k8.row.col.f32.tf32.tf32.f32 "
        "{%0,%1,%2,%3}, {%4,%5,%6,%7}, {%8,%9}, {%0,%1,%2,%3};"
        : "+f"(c[0]), "+f"(c[1]), "+f"(c[2]), "+f"(c[3])
        : "r"(a[0]), "r"(a[1]), "r"(a[2]), "r"(a[3]),
          "r"(b[0]), "r"(b[1]));
}

// ---------------- GEMM core: C[128x128] = A[128xK] * B[128xK]^T (both K-major)
#define BK 32
#define LDT 132   // 128 + 4 padding (bank-conflict mitigation)

__device__ __forceinline__ void gemm_body(const float* __restrict__ A,
                                          const float* __restrict__ B,
                                          int m0, int n0,
                                          float (&c)[2][8][4],
                                          unsigned* sA, unsigned* sB) {
    const int tid  = threadIdx.x;
    const int lane = tid & 31, warp = tid >> 5;
    const int wm = (warp & 3) * 32, wn = (warp >> 2) * 64;
    const int gid = lane >> 2, tig = lane & 3;

    for (int kc = 0; kc < DMODEL; kc += BK) {
        // stage A,B tiles transposed into smem as [k][row], converting to tf32
        #pragma unroll
        for (int i = 0; i < 4; i++) {
            int lin = tid + i * TPB;
            int row = lin >> 3;
            int kg  = (lin & 7) * 4;
            float4 av = *(const float4*)(A + (size_t)(m0 + row) * DMODEL + kc + kg);
            float4 bv = *(const float4*)(B + (size_t)(n0 + row) * DMODEL + kc + kg);
            sA[(kg + 0) * LDT + row] = f2tf(av.x);
            sA[(kg + 1) * LDT + row] = f2tf(av.y);
            sA[(kg + 2) * LDT + row] = f2tf(av.z);
            sA[(kg + 3) * LDT + row] = f2tf(av.w);
            sB[(kg + 0) * LDT + row] = f2tf(bv.x);
            sB[(kg + 1) * LDT + row] = f2tf(bv.y);
            sB[(kg + 2) * LDT + row] = f2tf(bv.z);
            sB[(kg + 3) * LDT + row] = f2tf(bv.w);
        }
        __syncthreads();

        #pragma unroll
        for (int ks = 0; ks < BK; ks += 8) {
            unsigned a[2][4], b[8][2];
            #pragma unroll
            for (int mt = 0; mt < 2; mt++) {
                int rb = wm + mt * 16 + gid;
                a[mt][0] = sA[(ks + tig) * LDT + rb];
                a[mt][1] = sA[(ks + tig) * LDT + rb + 8];
                a[mt][2] = sA[(ks + tig + 4) * LDT + rb];
                a[mt][3] = sA[(ks + tig + 4) * LDT + rb + 8];
            }
            #pragma unroll
            for (int nt = 0; nt < 8; nt++) {
                int cb = wn + nt * 8 + gid;
                b[nt][0] = sB[(ks + tig) * LDT + cb];
                b[nt][1] = sB[(ks + tig + 4) * LDT + cb];
            }
            #pragma unroll
            for (int mt = 0; mt < 2; mt++)
                #pragma unroll
                for (int nt = 0; nt < 8; nt++)
                    mma8(c[mt][nt], a[mt], b[nt]);
        }
        __syncthreads();
    }
}

// ---------------- QKV projection: out = x @ W^T + b, reindexed to [h][r][s'][d]
__global__ void __launch_bounds__(TPB) qkv_kernel(
    const float* __restrict__ x,
    const float* __restrict__ Wq, const float* __restrict__ bq,
    const float* __restrict__ Wk, const float* __restrict__ bk,
    const float* __restrict__ Wv, const float* __restrict__ bv,
    const float* __restrict__ beta)
{
    __shared__ unsigned sA[BK * LDT];
    __shared__ unsigned sB[BK * LDT];

    const int z = blockIdx.z;
    const float* W    = (z == 0) ? Wq : ((z == 1) ? Wk : Wv);
    const float* bias = (z == 0) ? bq : ((z == 1) ? bk : bv);
    float* outp       = (z == 0) ? g_q : ((z == 1) ? g_k : g_v);

    const int m0 = blockIdx.y * 128, n0 = blockIdx.x * 128;

    float c[2][8][4];
    #pragma unroll
    for (int mt = 0; mt < 2; mt++)
        #pragma unroll
        for (int nt = 0; nt < 8; nt++)
            #pragma unroll
            for (int k = 0; k < 4; k++) c[mt][nt][k] = 0.f;

    gemm_body(x, W, m0, n0, c, sA, sB);

    const int lane = threadIdx.x & 31, warp = threadIdx.x >> 5;
    const int wm = (warp & 3) * 32, wn = (warp >> 2) * 64;
    const int gid = lane >> 2, tig = lane & 3;

    #pragma unroll
    for (int mt = 0; mt < 2; mt++) {
        #pragma unroll
        for (int nt = 0; nt < 8; nt++) {
            int n_c = n0 + wn + nt * 8 + tig * 2;
            int h = n_c >> 6, d0 = n_c & 63;
            float sc = 1.0f;
            if (z == 0) sc = 0.125f * expf(-beta[h]);   // fold 1/(8*exp(beta)) into Q
            float b0 = bias[n_c], b1 = bias[n_c + 1];
            #pragma unroll
            for (int half = 0; half < 2; half++) {
                int s  = m0 + wm + mt * 16 + gid + half * 8;
                int rr = s & 3, sp = s >> 2;
                float v0 = (c[mt][nt][half * 2 + 0] + b0) * sc;
                float v1 = (c[mt][nt][half * 2 + 1] + b1) * sc;
                float2* dst = (float2*)(outp + (((h * 4 + rr) * SPRIME + sp) * DHEAD + d0));
                *dst = make_float2(v0, v1);
            }
        }
    }
}

// ---------------- output projection: out = ctx @ Wo^T + bo --------------------
__global__ void __launch_bounds__(TPB) oproj_kernel(
    const float* __restrict__ Wo, const float* __restrict__ bo,
    float* __restrict__ out)
{
    __shared__ unsigned sA[BK * LDT];
    __shared__ unsigned sB[BK * LDT];

    const int m0 = blockIdx.y * 128, n0 = blockIdx.x * 128;

    float c[2][8][4];
    #pragma unroll
    for (int mt = 0; mt < 2; mt++)
        #pragma unroll
        for (int nt = 0; nt < 8; nt++)
            #pragma unroll
            for (int k = 0; k < 4; k++) c[mt][nt][k] = 0.f;

    gemm_body(g_ctx, Wo, m0, n0, c, sA, sB);

    const int lane = threadIdx.x & 31, warp = threadIdx.x >> 5;
    const int wm = (warp & 3) * 32, wn = (warp >> 2) * 64;
    const int gid = lane >> 2, tig = lane & 3;

    #pragma unroll
    for (int mt = 0; mt < 2; mt++) {
        #pragma unroll
        for (int nt = 0; nt < 8; nt++) {
            int n_c = n0 + wn + nt * 8 + tig * 2;
            float b0 = bo[n_c], b1 = bo[n_c + 1];
            #pragma unroll
            for (int half = 0; half < 2; half++) {
                int mrow = m0 + wm + mt * 16 + gid + half * 8;
                float2* dst = (float2*)(out + (size_t)mrow * DMODEL + n_c);
                *dst = make_float2(c[mt][nt][half * 2 + 0] + b0,
                                   c[mt][nt][half * 2 + 1] + b1);
            }
        }
    }
}

// ---------------- attention over dilated windows ------------------------------
// One block per (query tile of 64, residue r, head h). Keys for local query q
// are the contiguous smem rows rk in [q, q+127] (rk = j' - (q0-127)), clipped
// by j' >= 0  <=>  rk >= 127 - q0. Note rk=191 is never consumed (max is
// 63+127=190) but is staged; it must be bounds-guarded against j >= SPRIME.
#define SQS 68     // stride of sQt / sV / sP rows (multiple of 4, pad 4)
#define SKS 196    // stride of sKt rows
#define ATTN_SMEM_FLOATS (64*SQS + 64*SKS + KTILE*SQS + KTILE*SQS)

__global__ void __launch_bounds__(TPB) attn_kernel() {
    extern __shared__ float sm[];
    float* sQt = sm;                       // [d=64][q=64]   stride SQS
    float* sKt = sQt + 64 * SQS;           // [d=64][rk=192] stride SKS
    float* sV  = sKt + 64 * SKS;           // [rk=192][d=64] stride SQS
    float* sP  = sV + KTILE * SQS;         // [rk=192][q=64] stride SQS

    const int tid = threadIdx.x;
    const int qt = blockIdx.x, r = blockIdx.y, h = blockIdx.z;
    const int q0 = qt * QTILE;
    const int kbase = q0 - 127;
    const float* Qb = g_q + (h * 4 + r) * SPRIME * DHEAD;
    const float* Kb = g_k + (h * 4 + r) * SPRIME * DHEAD;
    const float* Vb = g_v + (h * 4 + r) * SPRIME * DHEAD;

    // ---- stage Q transposed ----
    #pragma unroll
    for (int i = 0; i < 4; i++) {
        int lin = tid + i * TPB;
        int q = lin >> 4, dg = (lin & 15) * 4;
        float4 v = *(const float4*)(Qb + (q0 + q) * DHEAD + dg);
        sQt[(dg + 0) * SQS + q] = v.x;
        sQt[(dg + 1) * SQS + q] = v.y;
        sQt[(dg + 2) * SQS + q] = v.z;
        sQt[(dg + 3) * SQS + q] = v.w;
    }
    // ---- stage K transposed + V row-major (zero-fill j' < 0 and j' >= SPRIME)
    #pragma unroll
    for (int i = 0; i < 12; i++) {
        int lin = tid + i * TPB;
        int rk = lin >> 4, dg = (lin & 15) * 4;
        int j = kbase + rk;
        float4 kv = make_float4(0.f, 0.f, 0.f, 0.f);
        float4 vv = make_float4(0.f, 0.f, 0.f, 0.f);
        if (j >= 0 && j < SPRIME) {
            kv = *(const float4*)(Kb + j * DHEAD + dg);
            vv = *(const float4*)(Vb + j * DHEAD + dg);
        }
        sKt[(dg + 0) * SKS + rk] = kv.x;
        sKt[(dg + 1) * SKS + rk] = kv.y;
        sKt[(dg + 2) * SKS + rk] = kv.z;
        sKt[(dg + 3) * SKS + rk] = kv.w;
        *(float4*)(sV + rk * SQS + dg) = vv;
    }
    __syncthreads();

    // ---- phase 1: S[rk][q] = sum_d Q[q][d]*K[rk][d] ----
    {
        const int qb = (tid & 15) * 4;
        const int rb = (tid >> 4) * 12;
        float acc[12][4];
        #pragma unroll
        for (int j = 0; j < 12; j++)
            #pragma unroll
            for (int i = 0; i < 4; i++) acc[j][i] = 0.f;

        #pragma unroll 8
        for (int d = 0; d < DHEAD; d++) {
            float4 qv = *(const float4*)(sQt + d * SQS + qb);
            float4 k0 = *(const float4*)(sKt + d * SKS + rb);
            float4 k1 = *(const float4*)(sKt + d * SKS + rb + 4);
            float4 k2 = *(const float4*)(sKt + d * SKS + rb + 8);
            float kk[12] = {k0.x, k0.y, k0.z, k0.w, k1.x, k1.y,
                            k1.z, k1.w, k2.x, k2.y, k2.z, k2.w};
            #pragma unroll
            for (int j = 0; j < 12; j++) {
                acc[j][0] += kk[j] * qv.x;
                acc[j][1] += kk[j] * qv.y;
                acc[j][2] += kk[j] * qv.z;
                acc[j][3] += kk[j] * qv.w;
            }
        }
        #pragma unroll
        for (int j = 0; j < 12; j++)
            *(float4*)(sP + (rb + j) * SQS + qb) =
                make_float4(acc[j][0], acc[j][1], acc[j][2], acc[j][3]);
    }
    __syncthreads();

    // ---- phase 2: exact softmax per query over its band; zero the rest ----
    {
        const int q = tid >> 2, sub = tid & 3;
        int lo = q;
        int lim = 127 - q0;
        if (lim > lo) lo = lim;
        const int hi = q + 127;     // <= 190

        float mx = -3.0e38f;
        for (int rk = lo + sub; rk <= hi; rk += 4)
            mx = fmaxf(mx, sP[rk * SQS + q]);
        mx = fmaxf(mx, __shfl_xor_sync(0xffffffffu, mx, 1));
        mx = fmaxf(mx, __shfl_xor_sync(0xffffffffu, mx, 2));

        float sum = 0.f;
        for (int rk = lo + sub; rk <= hi; rk += 4)
            sum += expf(sP[rk * SQS + q] - mx);
        sum += __shfl_xor_sync(0xffffffffu, sum, 1);
        sum += __shfl_xor_sync(0xffffffffu, sum, 2);
        const float inv = 1.0f / sum;

        for (int rk = sub; rk < KTILE; rk += 4) {
            float p = 0.f;
            if (rk >= lo && rk <= hi)
                p = expf(sP[rk * SQS + q] - mx) * inv;
            sP[rk * SQS + q] = p;
        }
    }
    __syncthreads();

    // ---- phase 3: ctx[q][d] = sum_rk P[rk][q]*V[rk][d] ----
    {
        const int qb = (tid & 15) * 4;
        const int db = (tid >> 4) * 4;
        float acc[4][4];
        #pragma unroll
        for (int i = 0; i < 4; i++)
            #pragma unroll
            for (int j = 0; j < 4; j++) acc[i][j] = 0.f;

        #pragma unroll 4
        for (int rk = 0; rk < KTILE; rk++) {
            float4 pv = *(const float4*)(sP + rk * SQS + qb);
            float4 vv = *(const float4*)(sV + rk * SQS + db);
            float pr[4] = {pv.x, pv.y, pv.z, pv.w};
            #pragma unroll
            for (int i = 0; i < 4; i++) {
                acc[i][0] += pr[i] * vv.x;
                acc[i][1] += pr[i] * vv.y;
                acc[i][2] += pr[i] * vv.z;
                acc[i][3] += pr[i] * vv.w;
            }
        }
        #pragma unroll
        for (int i = 0; i < 4; i++) {
            int s = (q0 + qb + i) * 4 + r;      // undo dilation reindex
            *(float4*)(g_ctx + (size_t)s * DMODEL + h * DHEAD + db) =
                make_float4(acc[i][0], acc[i][1], acc[i][2], acc[i][3]);
        }
    }
}

// ---------------- launch ------------------------------------------------------
extern "C" void kernel_launch(void* const* d_in, const int* in_sizes, int n_in,
                              void* d_out, int out_size) {
    const float* x    = (const float*)d_in[0];
    const float* beta = (const float*)d_in[1];
    const float* Wq   = (const float*)d_in[2];
    const float* bq   = (const float*)d_in[3];
    const float* Wk   = (const float*)d_in[4];
    const float* bk   = (const float*)d_in[5];
    const float* Wv   = (const float*)d_in[6];
    const float* bv   = (const float*)d_in[7];
    const float* Wo   = (const float*)d_in[8];
    const float* bo   = (const float*)d_in[9];
    float* out = (float*)d_out;

    const int attn_smem = ATTN_SMEM_FLOATS * (int)sizeof(float);  // 172032 B
    cudaFuncSetAttribute(attn_kernel, cudaFuncAttributeMaxDynamicSharedMemorySize,
                         attn_smem);

    qkv_kernel<<<dim3(DMODEL / 128, SEQL / 128, 3), TPB>>>(x, Wq, bq, Wk, bk, Wv, bv, beta);
    attn_kernel<<<dim3(SPRIME / QTILE, 4, NHEAD), TPB, attn_smem>>>();
    oproj_kernel<<<dim3(DMODEL / 128, SEQL / 128), TPB>>>(Wo, bo, out);
}

// round 3
// speedup vs baseline: 1.0527x; 1.0527x over previous
#include <cuda_runtime.h>
#include <math.h>

#define TPB 256
#define SEQL 3072
#define DMODEL 1024
#define NHEAD 16
#define DHEAD 64
#define SPRIME 768      // SEQL / 4 (dilation)
#define KTILE 192       // 127 + 64 key rows per attention tile
#define QTILE 64

// ---------------- scratch (device globals; no allocation allowed) -------------
__device__ __align__(16) float g_q[NHEAD * 4 * SPRIME * DHEAD];
__device__ __align__(16) float g_k[NHEAD * 4 * SPRIME * DHEAD];
__device__ __align__(16) float g_v[NHEAD * 4 * SPRIME * DHEAD];
__device__ __align__(16) float g_ctx[SEQL * DMODEL];

// ---------------- tf32 helpers -----------------------------------------------
__device__ __forceinline__ unsigned f2tf(float f) {
    unsigned u;
    asm("cvt.rna.tf32.f32 %0, %1;" : "=r"(u) : "f"(f));
    return u;
}

__device__ __forceinline__ void mma8(float* c, const unsigned* a, const unsigned* b) {
    asm volatile(
        "mma.sync.aligned.m16n8k8.row.col.f32.tf32.tf32.f32 "
        "{%0,%1,%2,%3}, {%4,%5,%6,%7}, {%8,%9}, {%0,%1,%2,%3};"
        : "+f"(c[0]), "+f"(c[1]), "+f"(c[2]), "+f"(c[3])
        : "r"(a[0]), "r"(a[1]), "r"(a[2]), "r"(a[3]),
          "r"(b[0]), "r"(b[1]));
}

// ---------------- cp.async helpers --------------------------------------------
__device__ __forceinline__ void cpasync16(float* s, const float* g) {
    unsigned saddr = (unsigned)__cvta_generic_to_shared(s);
    asm volatile("cp.async.cg.shared.global [%0], [%1], 16;\n" :: "r"(saddr), "l"(g));
}
__device__ __forceinline__ void cpcommit() {
    asm volatile("cp.async.commit_group;\n");
}
template<int N> __device__ __forceinline__ void cpwait() {
    asm volatile("cp.async.wait_group %0;\n" :: "n"(N));
}

// ---------------- GEMM core: C[256x128] = A[256xK] * B[128xK]^T (both K-major)
// 8 warps: warp grid 4(m) x 2(n), warp tile 64x64 = 4 m16-tiles x 8 n8-tiles.
// smem row-major [row][k], stride 20 floats (conflict-free fragment loads),
// cp.async double-buffered, tf32 conversion after LDS.
#define BM 256
#define BN 128
#define BK 16
#define ASTR 20
#define NCHUNK (DMODEL / BK)
#define GEMM_SMEM_BYTES ((2 * BM * ASTR + 2 * BN * ASTR) * 4)   // 61440

__device__ __forceinline__ void gemm_body(const float* __restrict__ A,
                                          const float* __restrict__ B,
                                          int m0, int n0,
                                          float (&c)[4][8][4], float* sm) {
    float* sAb[2] = { sm, sm + BM * ASTR };
    float* sBb[2] = { sm + 2 * BM * ASTR, sm + 2 * BM * ASTR + BN * ASTR };

    const int tid  = threadIdx.x;
    const int lane = tid & 31, warp = tid >> 5;
    const int wm = (warp & 3) * 64, wn = (warp >> 2) * 64;
    const int gid = lane >> 2, tig = lane & 3;

    const int arow = tid;                       // A: one row per thread, 4 float4s
    const int brow = tid & 127, bkg = (tid >> 7) * 2;  // B: 2 threads per row

    // prologue: stage chunk 0 into buffer 0
    {
        const float* Ag = A + (size_t)(m0 + arow) * DMODEL;
        #pragma unroll
        for (int kg = 0; kg < 4; kg++)
            cpasync16(sAb[0] + arow * ASTR + kg * 4, Ag + kg * 4);
        const float* Bg = B + (size_t)(n0 + brow) * DMODEL;
        cpasync16(sBb[0] + brow * ASTR + bkg * 4, Bg + bkg * 4);
        cpasync16(sBb[0] + brow * ASTR + (bkg + 1) * 4, Bg + (bkg + 1) * 4);
        cpcommit();
    }

    for (int ch = 0; ch < NCHUNK; ch++) {
        if (ch + 1 < NCHUNK) {
            const int kc = (ch + 1) * BK;
            const int nb = (ch + 1) & 1;
            const float* Ag = A + (size_t)(m0 + arow) * DMODEL + kc;
            #pragma unroll
            for (int kg = 0; kg < 4; kg++)
                cpasync16(sAb[nb] + arow * ASTR + kg * 4, Ag + kg * 4);
            const float* Bg = B + (size_t)(n0 + brow) * DMODEL + kc;
            cpasync16(sBb[nb] + brow * ASTR + bkg * 4, Bg + bkg * 4);
            cpasync16(sBb[nb] + brow * ASTR + (bkg + 1) * 4, Bg + (bkg + 1) * 4);
            cpcommit();
            cpwait<1>();
        } else {
            cpwait<0>();
        }
        __syncthreads();

        const float* a_s = sAb[ch & 1];
        const float* b_s = sBb[ch & 1];

        #pragma unroll
        for (int ks = 0; ks < BK; ks += 8) {
            unsigned a[4][4], b[8][2];
            #pragma unroll
            for (int mt = 0; mt < 4; mt++) {
                int rb = wm + mt * 16 + gid;
                a[mt][0] = f2tf(a_s[rb * ASTR + ks + tig]);
                a[mt][1] = f2tf(a_s[(rb + 8) * ASTR + ks + tig]);
                a[mt][2] = f2tf(a_s[rb * ASTR + ks + tig + 4]);
                a[mt][3] = f2tf(a_s[(rb + 8) * ASTR + ks + tig + 4]);
            }
            #pragma unroll
            for (int nt = 0; nt < 8; nt++) {
                int cb = wn + nt * 8 + gid;
                b[nt][0] = f2tf(b_s[cb * ASTR + ks + tig]);
                b[nt][1] = f2tf(b_s[cb * ASTR + ks + tig + 4]);
            }
            #pragma unroll
            for (int mt = 0; mt < 4; mt++)
                #pragma unroll
                for (int nt = 0; nt < 8; nt++)
                    mma8(c[mt][nt], a[mt], b[nt]);
        }
        __syncthreads();
    }
}

// ---------------- QKV projection: out = x @ W^T + b, reindexed to [h][r][s'][d]
__global__ void __launch_bounds__(TPB) qkv_kernel(
    const float* __restrict__ x,
    const float* __restrict__ Wq, const float* __restrict__ bq,
    const float* __restrict__ Wk, const float* __restrict__ bk,
    const float* __restrict__ Wv, const float* __restrict__ bv,
    const float* __restrict__ beta)
{
    extern __shared__ float sm[];

    const int z = blockIdx.z;
    const float* W    = (z == 0) ? Wq : ((z == 1) ? Wk : Wv);
    const float* bias = (z == 0) ? bq : ((z == 1) ? bk : bv);
    float* outp       = (z == 0) ? g_q : ((z == 1) ? g_k : g_v);

    const int m0 = blockIdx.y * BM, n0 = blockIdx.x * BN;

    float c[4][8][4];
    #pragma unroll
    for (int mt = 0; mt < 4; mt++)
        #pragma unroll
        for (int nt = 0; nt < 8; nt++)
            #pragma unroll
            for (int k = 0; k < 4; k++) c[mt][nt][k] = 0.f;

    gemm_body(x, W, m0, n0, c, sm);

    const int lane = threadIdx.x & 31, warp = threadIdx.x >> 5;
    const int wm = (warp & 3) * 64, wn = (warp >> 2) * 64;
    const int gid = lane >> 2, tig = lane & 3;

    #pragma unroll
    for (int mt = 0; mt < 4; mt++) {
        #pragma unroll
        for (int nt = 0; nt < 8; nt++) {
            int n_c = n0 + wn + nt * 8 + tig * 2;
            int h = n_c >> 6, d0 = n_c & 63;
            float sc = 1.0f;
            if (z == 0) sc = 0.125f * expf(-beta[h]);   // fold 1/(8*exp(beta)) into Q
            float b0 = bias[n_c], b1 = bias[n_c + 1];
            #pragma unroll
            for (int half = 0; half < 2; half++) {
                int s  = m0 + wm + mt * 16 + gid + half * 8;
                int rr = s & 3, sp = s >> 2;
                float v0 = (c[mt][nt][half * 2 + 0] + b0) * sc;
                float v1 = (c[mt][nt][half * 2 + 1] + b1) * sc;
                float2* dst = (float2*)(outp + (((h * 4 + rr) * SPRIME + sp) * DHEAD + d0));
                *dst = make_float2(v0, v1);
            }
        }
    }
}

// ---------------- output projection: out = ctx @ Wo^T + bo --------------------
__global__ void __launch_bounds__(TPB) oproj_kernel(
    const float* __restrict__ Wo, const float* __restrict__ bo,
    float* __restrict__ out)
{
    extern __shared__ float sm[];

    const int m0 = blockIdx.y * BM, n0 = blockIdx.x * BN;

    float c[4][8][4];
    #pragma unroll
    for (int mt = 0; mt < 4; mt++)
        #pragma unroll
        for (int nt = 0; nt < 8; nt++)
            #pragma unroll
            for (int k = 0; k < 4; k++) c[mt][nt][k] = 0.f;

    gemm_body(g_ctx, Wo, m0, n0, c, sm);

    const int lane = threadIdx.x & 31, warp = threadIdx.x >> 5;
    const int wm = (warp & 3) * 64, wn = (warp >> 2) * 64;
    const int gid = lane >> 2, tig = lane & 3;

    #pragma unroll
    for (int mt = 0; mt < 4; mt++) {
        #pragma unroll
        for (int nt = 0; nt < 8; nt++) {
            int n_c = n0 + wn + nt * 8 + tig * 2;
            float b0 = bo[n_c], b1 = bo[n_c + 1];
            #pragma unroll
            for (int half = 0; half < 2; half++) {
                int mrow = m0 + wm + mt * 16 + gid + half * 8;
                float2* dst = (float2*)(out + (size_t)mrow * DMODEL + n_c);
                *dst = make_float2(c[mt][nt][half * 2 + 0] + b0,
                                   c[mt][nt][half * 2 + 1] + b1);
            }
        }
    }
}

// ---------------- attention over dilated windows (tensor-core version) --------
// One block per (query tile of 64, residue r, head h). smem layouts:
//   sQ  [q=64][d=64]    stride SQR (A for S=QK^T, row-major m x k)
//   sK  [rk=192][d=64]  stride SQR (B for S: n x k, k-major)
//   sVt [d=64][rk=192]  stride SSR (B for ctx=P.V: n x k, k-major)
//   sS  [q=64][rk=192]  stride SSR (C of phase1 / A of phase3)
// Phase1 uses 3xTF32 split (fp32-grade scores); phase3 single tf32.
#define SQR 68
#define SSR 196
#define ATTN_SMEM_BYTES ((64 * SQR + KTILE * SQR + 64 * SSR + 64 * SSR) * 4)  // 169984

__global__ void __launch_bounds__(TPB) attn_kernel() {
    extern __shared__ float smA[];
    float* sQ  = smA;                      // [64][SQR]
    float* sK  = sQ + 64 * SQR;            // [192][SQR]
    float* sVt = sK + KTILE * SQR;         // [64][SSR]
    float* sS  = sVt + 64 * SSR;           // [64][SSR]

    const int tid = threadIdx.x;
    const int lane = tid & 31, warp = tid >> 5;
    const int gid = lane >> 2, tig = lane & 3;
    const int qt = blockIdx.x, r = blockIdx.y, h = blockIdx.z;
    const int q0 = qt * QTILE;
    const int kbase = q0 - 127;
    const float* Qb = g_q + (h * 4 + r) * SPRIME * DHEAD;
    const float* Kb = g_k + (h * 4 + r) * SPRIME * DHEAD;
    const float* Vb = g_v + (h * 4 + r) * SPRIME * DHEAD;

    // ---- stage Q row-major ----
    #pragma unroll
    for (int i = 0; i < 4; i++) {
        int lin = tid + i * TPB;
        int q = lin >> 4, dg = (lin & 15) * 4;
        *(float4*)(sQ + q * SQR + dg) = *(const float4*)(Qb + (q0 + q) * DHEAD + dg);
    }
    // ---- stage K row-major + V transposed (zero-fill out-of-range j) ----
    #pragma unroll
    for (int i = 0; i < 12; i++) {
        int lin = tid + i * TPB;
        int rk = lin >> 4, dg = (lin & 15) * 4;
        int j = kbase + rk;
        float4 kv = make_float4(0.f, 0.f, 0.f, 0.f);
        float4 vv = make_float4(0.f, 0.f, 0.f, 0.f);
        if (j >= 0 && j < SPRIME) {
            kv = *(const float4*)(Kb + j * DHEAD + dg);
            vv = *(const float4*)(Vb + j * DHEAD + dg);
        }
        *(float4*)(sK + rk * SQR + dg) = kv;
        sVt[(dg + 0) * SSR + rk] = vv.x;
        sVt[(dg + 1) * SSR + rk] = vv.y;
        sVt[(dg + 2) * SSR + rk] = vv.z;
        sVt[(dg + 3) * SSR + rk] = vv.w;
    }
    __syncthreads();

    // ---- phase 1: S[q][rk] = Q.K^T via 3xTF32 mma ----
    // warp grid: 4(m) x 2(n); warp tile = 16 q x 96 rk (12 n8-tiles)
    {
        const int wm4 = (warp & 3) * 16, wn2 = (warp >> 2) * 96;
        float c[12][4];
        #pragma unroll
        for (int nt = 0; nt < 12; nt++)
            #pragma unroll
            for (int k = 0; k < 4; k++) c[nt][k] = 0.f;

        #pragma unroll
        for (int ks = 0; ks < DHEAD; ks += 8) {
            unsigned ah[4], al[4];
            const int rq = wm4 + gid;
            {
                float x0 = sQ[rq * SQR + ks + tig];
                float x1 = sQ[(rq + 8) * SQR + ks + tig];
                float x2 = sQ[rq * SQR + ks + tig + 4];
                float x3 = sQ[(rq + 8) * SQR + ks + tig + 4];
                ah[0] = f2tf(x0); al[0] = f2tf(x0 - __uint_as_float(ah[0]));
                ah[1] = f2tf(x1); al[1] = f2tf(x1 - __uint_as_float(ah[1]));
                ah[2] = f2tf(x2); al[2] = f2tf(x2 - __uint_as_float(ah[2]));
                ah[3] = f2tf(x3); al[3] = f2tf(x3 - __uint_as_float(ah[3]));
            }
            #pragma unroll
            for (int nt = 0; nt < 12; nt++) {
                int cb = wn2 + nt * 8 + gid;
                float y0 = sK[cb * SQR + ks + tig];
                float y1 = sK[cb * SQR + ks + tig + 4];
                unsigned bh[2], bl[2];
                bh[0] = f2tf(y0); bl[0] = f2tf(y0 - __uint_as_float(bh[0]));
                bh[1] = f2tf(y1); bl[1] = f2tf(y1 - __uint_as_float(bh[1]));
                mma8(c[nt], ah, bh);
                mma8(c[nt], ah, bl);
                mma8(c[nt], al, bh);
            }
        }
        #pragma unroll
        for (int nt = 0; nt < 12; nt++) {
            int col = wn2 + nt * 8 + tig * 2;
            *(float2*)(sS + (wm4 + gid) * SSR + col) = make_float2(c[nt][0], c[nt][1]);
            *(float2*)(sS + (wm4 + gid + 8) * SSR + col) = make_float2(c[nt][2], c[nt][3]);
        }
    }
    __syncthreads();

    // ---- phase 2: exact softmax per query over its band; zero the rest ----
    {
        const int q = tid >> 2, sub = tid & 3;
        int lo = q;
        int lim = 127 - q0;
        if (lim > lo) lo = lim;
        const int hi = q + 127;     // <= 190
        float* row = sS + q * SSR;

        float mx = -3.0e38f;
        for (int rk = lo + sub; rk <= hi; rk += 4)
            mx = fmaxf(mx, row[rk]);
        mx = fmaxf(mx, __shfl_xor_sync(0xffffffffu, mx, 1));
        mx = fmaxf(mx, __shfl_xor_sync(0xffffffffu, mx, 2));

        float sum = 0.f;
        for (int rk = lo + sub; rk <= hi; rk += 4)
            sum += expf(row[rk] - mx);
        sum += __shfl_xor_sync(0xffffffffu, sum, 1);
        sum += __shfl_xor_sync(0xffffffffu, sum, 2);
        const float inv = 1.0f / sum;

        for (int rk = sub; rk < KTILE; rk += 4) {
            float p = 0.f;
            if (rk >= lo && rk <= hi)
                p = expf(row[rk] - mx) * inv;
            row[rk] = p;
        }
    }
    __syncthreads();

    // ---- phase 3: ctx[q][d] = P.V via tf32 mma ----
    // warp grid: 4(m) x 2(n); warp tile = 16 q x 32 d (4 n8-tiles), k = 192
    {
        const int wm4 = (warp & 3) * 16, wn3 = (warp >> 2) * 32;
        float c[4][4];
        #pragma unroll
        for (int nt = 0; nt < 4; nt++)
            #pragma unroll
            for (int k = 0; k < 4; k++) c[nt][k] = 0.f;

        #pragma unroll 4
        for (int ks = 0; ks < KTILE; ks += 8) {
            unsigned a[4], b[4][2];
            const int rq = wm4 + gid;
            a[0] = f2tf(sS[rq * SSR + ks + tig]);
            a[1] = f2tf(sS[(rq + 8) * SSR + ks + tig]);
            a[2] = f2tf(sS[rq * SSR + ks + tig + 4]);
            a[3] = f2tf(sS[(rq + 8) * SSR + ks + tig + 4]);
            #pragma unroll
            for (int nt = 0; nt < 4; nt++) {
                int dn = wn3 + nt * 8 + gid;
                b[nt][0] = f2tf(sVt[dn * SSR + ks + tig]);
                b[nt][1] = f2tf(sVt[dn * SSR + ks + tig + 4]);
            }
            #pragma unroll
            for (int nt = 0; nt < 4; nt++)
                mma8(c[nt], a, b[nt]);
        }
        #pragma unroll
        for (int nt = 0; nt < 4; nt++) {
            int dn = wn3 + nt * 8 + tig * 2;
            #pragma unroll
            for (int half = 0; half < 2; half++) {
                int ql = wm4 + gid + half * 8;
                int s = (q0 + ql) * 4 + r;      // undo dilation reindex
                *(float2*)(g_ctx + (size_t)s * DMODEL + h * DHEAD + dn) =
                    make_float2(c[nt][half * 2 + 0], c[nt][half * 2 + 1]);
            }
        }
    }
}

// ---------------- launch ------------------------------------------------------
extern "C" void kernel_launch(void* const* d_in, const int* in_sizes, int n_in,
                              void* d_out, int out_size) {
    const float* x    = (const float*)d_in[0];
    const float* beta = (const float*)d_in[1];
    const float* Wq   = (const float*)d_in[2];
    const float* bq   = (const float*)d_in[3];
    const float* Wk   = (const float*)d_in[4];
    const float* bk   = (const float*)d_in[5];
    const float* Wv   = (const float*)d_in[6];
    const float* bv   = (const float*)d_in[7];
    const float* Wo   = (const float*)d_in[8];
    const float* bo   = (const float*)d_in[9];
    float* out = (float*)d_out;

    cudaFuncSetAttribute(qkv_kernel, cudaFuncAttributeMaxDynamicSharedMemorySize,
                         GEMM_SMEM_BYTES);
    cudaFuncSetAttribute(oproj_kernel, cudaFuncAttributeMaxDynamicSharedMemorySize,
                         GEMM_SMEM_BYTES);
    cudaFuncSetAttribute(attn_kernel, cudaFuncAttributeMaxDynamicSharedMemorySize,
                         ATTN_SMEM_BYTES);

    qkv_kernel<<<dim3(DMODEL / BN, SEQL / BM, 3), TPB, GEMM_SMEM_BYTES>>>(
        x, Wq, bq, Wk, bk, Wv, bv, beta);
    attn_kernel<<<dim3(SPRIME / QTILE, 4, NHEAD), TPB, ATTN_SMEM_BYTES>>>();
    oproj_kernel<<<dim3(DMODEL / BN, SEQL / BM), TPB, GEMM_SMEM_BYTES>>>(Wo, bo, out);
}

// round 12
// speedup vs baseline: 1.6772x; 1.5933x over previous
#include <cuda_runtime.h>
#include <math.h>
#include <stdint.h>

#define TPB 256
#define SEQL 3072
#define DMODEL 1024
#define NHEAD 16
#define DHEAD 64
#define SPRIME 768      // SEQL / 4 (dilation)
#define KTILE 192       // 127 + 64 key rows per attention tile
#define QTILE 64
#define KBLKS (DMODEL / 8)   // 128

// ---------------- scratch (device globals; no allocation allowed) -------------
__device__ __align__(16) float g_q[NHEAD * 4 * SPRIME * DHEAD];
__device__ __align__(16) float g_k[NHEAD * 4 * SPRIME * DHEAD];
__device__ __align__(16) float g_v[NHEAD * 4 * SPRIME * DHEAD];
__device__ __align__(16) float g_ctx[SEQL * DMODEL];
// fragment-packed operands (tf32-rounded):
__device__ __align__(16) float g_packX[SEQL * DMODEL];       // A-frag pack of x
__device__ __align__(16) float g_packC[SEQL * DMODEL];       // A-frag pack of ctx
__device__ __align__(16) float g_packW[4 * DMODEL * DMODEL]; // B-frag packs Wq,Wk,Wv,Wo

// ---------------- tf32 helpers -----------------------------------------------
__device__ __forceinline__ unsigned f2tf(float f) {
    unsigned u;
    asm("cvt.rna.tf32.f32 %0, %1;" : "=r"(u) : "f"(f));
    return u;
}

__device__ __forceinline__ void mma8(float* c, const unsigned* a, const unsigned* b) {
    asm volatile(
        "mma.sync.aligned.m16n8k8.row.col.f32.tf32.tf32.f32 "
        "{%0,%1,%2,%3}, {%4,%5,%6,%7}, {%8,%9}, {%0,%1,%2,%3};"
        : "+f"(c[0]), "+f"(c[1]), "+f"(c[2]), "+f"(c[3])
        : "r"(a[0]), "r"(a[1]), "r"(a[2]), "r"(a[3]),
          "r"(b[0]), "r"(b[1]));
}

// ---------------- cp.async helpers --------------------------------------------
__device__ __forceinline__ void cpasync16(void* s, const void* g) {
    unsigned saddr = (unsigned)__cvta_generic_to_shared(s);
    asm volatile("cp.async.cg.shared.global [%0], [%1], 16;\n" :: "r"(saddr), "l"(g));
}
__device__ __forceinline__ void cpcommit() {
    asm volatile("cp.async.commit_group;\n");
}
template<int N> __device__ __forceinline__ void cpwait() {
    asm volatile("cp.async.wait_group %0;\n" :: "n"(N));
}

// ---------------- pack kernels -------------------------------------------------
// A-frag pack: dst[((MB*KBLKS + KB)*32 + lane)*4 + j], lane=(gid<<2)|tig,
//   j0=A[MB*16+gid][KB*8+tig]  j1=A[..+8][..]  j2=A[..][..+4]  j3=A[..+8][..+4]
// mode 0: src = xsrc (harness input), dst = g_packX
// mode 1: src = g_ctx (device global), dst = g_packC
__global__ void __launch_bounds__(256) pack_a_kernel(const float* __restrict__ xsrc,
                                                     int mode) {
    const float* src = (mode == 0) ? xsrc : g_ctx;
    float* dst       = (mode == 0) ? g_packX : g_packC;
    const unsigned u = blockIdx.x * 256 + threadIdx.x;   // one float4 out
    const unsigned l = u & 31, blk = u >> 5;
    const unsigned KB = blk & (KBLKS - 1), MB = blk >> 7;
    const unsigned gid = l >> 2, tig = l & 3;
    const float* p = src + (size_t)(MB * 16 + gid) * DMODEL + KB * 8 + tig;
    uint4 o;
    o.x = f2tf(p[0]);
    o.y = f2tf(p[8 * DMODEL]);
    o.z = f2tf(p[4]);
    o.w = f2tf(p[8 * DMODEL + 4]);
    *((uint4*)dst + u) = o;
}

// B-frag pack: dst[((NB*KBLKS + KB)*32 + lane)*2 + e],
//   e0=W[NB*8+gid][KB*8+tig]  e1=W[NB*8+gid][KB*8+tig+4]
__global__ void __launch_bounds__(256) pack_b_kernel(
    const float* __restrict__ Wq, const float* __restrict__ Wk,
    const float* __restrict__ Wv, const float* __restrict__ Wo) {
    const int z = blockIdx.y;
    const float* W = (z == 0) ? Wq : ((z == 1) ? Wk : ((z == 2) ? Wv : Wo));
    float* dst = g_packW + (size_t)z * DMODEL * DMODEL;
    const unsigned u = blockIdx.x * 256 + threadIdx.x;   // one float2 out
    const unsigned l = u & 31, blk = u >> 5;
    const unsigned KB = blk & (KBLKS - 1), NB = blk >> 7;
    const unsigned gid = l >> 2, tig = l & 3;
    const float* p = W + (size_t)(NB * 8 + gid) * DMODEL + KB * 8 + tig;
    uint2 o;
    o.x = f2tf(p[0]);
    o.y = f2tf(p[4]);
    *((uint2*)dst + u) = o;
}

// ---------------- packed-fragment GEMM: C[128x128] -----------------------------
// 8 warps (4m x 2n), warp tile 32x64 = 2 m16-tiles x 8 n8-tiles.
// BK=32 (4 k8 blocks), double-buffered cp.async from packed operands.
// smem chunk layouts:  A [i(8)][j(4)][lane(32)][4]f  B [inb(16)][j(4)][lane(32)][2]f
#define GBK 32
#define GNCH (DMODEL / GBK)                  // 32
#define CHUNK_F 4096                         // floats per operand chunk (16KB)
#define GEMM_SMEM_BYTES (4 * CHUNK_F * 4)    // 65536

__device__ __forceinline__ void gemm_body(const float* __restrict__ Ap,
                                          const float* __restrict__ Bp,
                                          int mb0, int nb0,
                                          float (&c)[2][8][4], float* sm) {
    float* sA[2] = { sm, sm + CHUNK_F };
    float* sB[2] = { sm + 2 * CHUNK_F, sm + 3 * CHUNK_F };

    const int tid  = threadIdx.x;
    const int lane = tid & 31, warp = tid >> 5;
    const int wm2 = (warp & 3) * 2;     // chunk-local mblk base
    const int wn8 = (warp >> 2) * 8;    // chunk-local nblk base

    // ---- stage one chunk (ch) into buffer b ----
    auto stage = [&](int ch, int b) {
        const int kb0 = ch * 4;
        #pragma unroll
        for (int t = 0; t < 4; t++) {
            unsigned u = tid + t * 256;            // A 16B-unit
            unsigned i = u >> 7, j = (u >> 5) & 3, l = u & 31;
            const float* srcA = Ap + ((size_t)((mb0 + i) * KBLKS + kb0 + j) * 32 + l) * 4;
            cpasync16(sA[b] + u * 4, srcA);
        }
        #pragma unroll
        for (int t = 0; t < 4; t++) {
            unsigned u = tid + t * 256;            // B 16B-unit (2 lanes x float2)
            unsigned inb = u >> 6, rem = u & 63;
            unsigned j = rem >> 4, lp = (rem & 15) * 2;
            const float* srcB = Bp + ((size_t)((nb0 + inb) * KBLKS + kb0 + j) * 32 + lp) * 2;
            cpasync16(sB[b] + u * 4, srcB);
        }
        cpcommit();
    };

    stage(0, 0);

    for (int ch = 0; ch < GNCH; ch++) {
        const int b = ch & 1;
        if (ch + 1 < GNCH) { stage(ch + 1, b ^ 1); cpwait<1>(); }
        else               { cpwait<0>(); }
        __syncthreads();

        const float* a_s = sA[b];
        const float* b_s = sB[b];
        #pragma unroll
        for (int ks8 = 0; ks8 < 4; ks8++) {
            uint4 a[2];
            uint2 bb[8];
            #pragma unroll
            for (int mt = 0; mt < 2; mt++)
                a[mt] = *(const uint4*)(a_s + (((wm2 + mt) * 4 + ks8) * 32 + lane) * 4);
            #pragma unroll
            for (int nt = 0; nt < 8; nt++)
                bb[nt] = *(const uint2*)(b_s + (((wn8 + nt) * 4 + ks8) * 32 + lane) * 2);
            #pragma unroll
            for (int mt = 0; mt < 2; mt++)
                #pragma unroll
                for (int nt = 0; nt < 8; nt++)
                    mma8(c[mt][nt], (const unsigned*)&a[mt], (const unsigned*)&bb[nt]);
        }
        __syncthreads();
    }
}

// ---------------- QKV projection -----------------------------------------------
__global__ void __launch_bounds__(TPB, 2) qkv_kernel(
    const float* __restrict__ bq, const float* __restrict__ bk,
    const float* __restrict__ bv, const float* __restrict__ beta)
{
    extern __shared__ float sm[];
    const int z = blockIdx.z;
    const float* Bp   = g_packW + (size_t)z * DMODEL * DMODEL;
    const float* bias = (z == 0) ? bq : ((z == 1) ? bk : bv);
    float* outp       = (z == 0) ? g_q : ((z == 1) ? g_k : g_v);
    const int m0 = blockIdx.y * 128, n0 = blockIdx.x * 128;

    float c[2][8][4];
    #pragma unroll
    for (int mt = 0; mt < 2; mt++)
        #pragma unroll
        for (int nt = 0; nt < 8; nt++)
            #pragma unroll
            for (int k = 0; k < 4; k++) c[mt][nt][k] = 0.f;

    gemm_body(g_packX, Bp, m0 / 16, n0 / 8, c, sm);

    const int lane = threadIdx.x & 31, warp = threadIdx.x >> 5;
    const int wm = (warp & 3) * 32, wn = (warp >> 2) * 64;
    const int gid = lane >> 2, tig = lane & 3;

    #pragma unroll
    for (int mt = 0; mt < 2; mt++) {
        #pragma unroll
        for (int nt = 0; nt < 8; nt++) {
            int n_c = n0 + wn + nt * 8 + tig * 2;
            int h = n_c >> 6, d0 = n_c & 63;
            float sc = 1.0f;
            if (z == 0) sc = 0.125f * expf(-beta[h]);   // fold 1/(8*exp(beta)) into Q
            float b0 = bias[n_c], b1 = bias[n_c + 1];
            #pragma unroll
            for (int half = 0; half < 2; half++) {
                int s  = m0 + wm + mt * 16 + gid + half * 8;
                int rr = s & 3, sp = s >> 2;
                float v0 = (c[mt][nt][half * 2 + 0] + b0) * sc;
                float v1 = (c[mt][nt][half * 2 + 1] + b1) * sc;
                float2* dst = (float2*)(outp + (((h * 4 + rr) * SPRIME + sp) * DHEAD + d0));
                *dst = make_float2(v0, v1);
            }
        }
    }
}

// ---------------- output projection --------------------------------------------
__global__ void __launch_bounds__(TPB, 2) oproj_kernel(
    const float* __restrict__ bo, float* __restrict__ out)
{
    extern __shared__ float sm[];
    const int m0 = blockIdx.y * 128, n0 = blockIdx.x * 128;

    float c[2][8][4];
    #pragma unroll
    for (int mt = 0; mt < 2; mt++)
        #pragma unroll
        for (int nt = 0; nt < 8; nt++)
            #pragma unroll
            for (int k = 0; k < 4; k++) c[mt][nt][k] = 0.f;

    gemm_body(g_packC, g_packW + (size_t)3 * DMODEL * DMODEL, m0 / 16, n0 / 8, c, sm);

    const int lane = threadIdx.x & 31, warp = threadIdx.x >> 5;
    const int wm = (warp & 3) * 32, wn = (warp >> 2) * 64;
    const int gid = lane >> 2, tig = lane & 3;

    #pragma unroll
    for (int mt = 0; mt < 2; mt++) {
        #pragma unroll
        for (int nt = 0; nt < 8; nt++) {
            int n_c = n0 + wn + nt * 8 + tig * 2;
            float b0 = bo[n_c], b1 = bo[n_c + 1];
            #pragma unroll
            for (int half = 0; half < 2; half++) {
                int mrow = m0 + wm + mt * 16 + gid + half * 8;
                float2* dst = (float2*)(out + (size_t)mrow * DMODEL + n_c);
                *dst = make_float2(c[mt][nt][half * 2 + 0] + b0,
                                   c[mt][nt][half * 2 + 1] + b1);
            }
        }
    }
}

// ---------------- attention over dilated windows (legacy mma) -------------------
#define SQR 68
#define SSR 196
#define ATTN_SMEM_BYTES ((64 * SQR + KTILE * SQR + 64 * SSR + 64 * SSR) * 4)  // 169984

__global__ void __launch_bounds__(TPB) attn_kernel() {
    extern __shared__ float smA[];
    float* sQ  = smA;                      // [64][SQR]
    float* sK  = sQ + 64 * SQR;            // [192][SQR]
    float* sVt = sK + KTILE * SQR;         // [64][SSR]
    float* sS  = sVt + 64 * SSR;           // [64][SSR]

    const int tid = threadIdx.x;
    const int lane = tid & 31, warp = tid >> 5;
    const int gid = lane >> 2, tig = lane & 3;
    const int qt = blockIdx.x, r = blockIdx.y, h = blockIdx.z;
    const int q0 = qt * QTILE;
    const int kbase = q0 - 127;
    const float* Qb = g_q + (h * 4 + r) * SPRIME * DHEAD;
    const float* Kb = g_k + (h * 4 + r) * SPRIME * DHEAD;
    const float* Vb = g_v + (h * 4 + r) * SPRIME * DHEAD;

    #pragma unroll
    for (int i = 0; i < 4; i++) {
        int lin = tid + i * TPB;
        int q = lin >> 4, dg = (lin & 15) * 4;
        *(float4*)(sQ + q * SQR + dg) = *(const float4*)(Qb + (q0 + q) * DHEAD + dg);
    }
    #pragma unroll
    for (int i = 0; i < 12; i++) {
        int lin = tid + i * TPB;
        int rk = lin >> 4, dg = (lin & 15) * 4;
        int j = kbase + rk;
        float4 kv = make_float4(0.f, 0.f, 0.f, 0.f);
        float4 vv = make_float4(0.f, 0.f, 0.f, 0.f);
        if (j >= 0 && j < SPRIME) {
            kv = *(const float4*)(Kb + j * DHEAD + dg);
            vv = *(const float4*)(Vb + j * DHEAD + dg);
        }
        *(float4*)(sK + rk * SQR + dg) = kv;
        sVt[(dg + 0) * SSR + rk] = vv.x;
        sVt[(dg + 1) * SSR + rk] = vv.y;
        sVt[(dg + 2) * SSR + rk] = vv.z;
        sVt[(dg + 3) * SSR + rk] = vv.w;
    }
    __syncthreads();

    // ---- phase 1: S = Q.K^T via 3xTF32 ----
    {
        const int wm4 = (warp & 3) * 16, wn2 = (warp >> 2) * 96;
        float c[12][4];
        #pragma unroll
        for (int nt = 0; nt < 12; nt++)
            #pragma unroll
            for (int k = 0; k < 4; k++) c[nt][k] = 0.f;

        #pragma unroll
        for (int ks = 0; ks < DHEAD; ks += 8) {
            unsigned ah[4], al[4];
            const int rq = wm4 + gid;
            {
                float x0 = sQ[rq * SQR + ks + tig];
                float x1 = sQ[(rq + 8) * SQR + ks + tig];
                float x2 = sQ[rq * SQR + ks + tig + 4];
                float x3 = sQ[(rq + 8) * SQR + ks + tig + 4];
                ah[0] = f2tf(x0); al[0] = f2tf(x0 - __uint_as_float(ah[0]));
                ah[1] = f2tf(x1); al[1] = f2tf(x1 - __uint_as_float(ah[1]));
                ah[2] = f2tf(x2); al[2] = f2tf(x2 - __uint_as_float(ah[2]));
                ah[3] = f2tf(x3); al[3] = f2tf(x3 - __uint_as_float(ah[3]));
            }
            #pragma unroll
            for (int nt = 0; nt < 12; nt++) {
                int cb = wn2 + nt * 8 + gid;
                float y0 = sK[cb * SQR + ks + tig];
                float y1 = sK[cb * SQR + ks + tig + 4];
                unsigned bh[2], bl[2];
                bh[0] = f2tf(y0); bl[0] = f2tf(y0 - __uint_as_float(bh[0]));
                bh[1] = f2tf(y1); bl[1] = f2tf(y1 - __uint_as_float(bh[1]));
                mma8(c[nt], ah, bh);
                mma8(c[nt], ah, bl);
                mma8(c[nt], al, bh);
            }
        }
        #pragma unroll
        for (int nt = 0; nt < 12; nt++) {
            int col = wn2 + nt * 8 + tig * 2;
            *(float2*)(sS + (wm4 + gid) * SSR + col) = make_float2(c[nt][0], c[nt][1]);
            *(float2*)(sS + (wm4 + gid + 8) * SSR + col) = make_float2(c[nt][2], c[nt][3]);
        }
    }
    __syncthreads();

    // ---- phase 2: softmax per query over its band ----
    {
        const int q = tid >> 2, sub = tid & 3;
        int lo = q;
        int lim = 127 - q0;
        if (lim > lo) lo = lim;
        const int hi = q + 127;
        float* row = sS + q * SSR;

        float mx = -3.0e38f;
        for (int rk = lo + sub; rk <= hi; rk += 4)
            mx = fmaxf(mx, row[rk]);
        mx = fmaxf(mx, __shfl_xor_sync(0xffffffffu, mx, 1));
        mx = fmaxf(mx, __shfl_xor_sync(0xffffffffu, mx, 2));

        float sum = 0.f;
        for (int rk = lo + sub; rk <= hi; rk += 4)
            sum += expf(row[rk] - mx);
        sum += __shfl_xor_sync(0xffffffffu, sum, 1);
        sum += __shfl_xor_sync(0xffffffffu, sum, 2);
        const float inv = 1.0f / sum;

        for (int rk = sub; rk < KTILE; rk += 4) {
            float p = 0.f;
            if (rk >= lo && rk <= hi)
                p = expf(row[rk] - mx) * inv;
            row[rk] = p;
        }
    }
    __syncthreads();

    // ---- phase 3: ctx = P.V via tf32 mma ----
    {
        const int wm4 = (warp & 3) * 16, wn3 = (warp >> 2) * 32;
        float c[4][4];
        #pragma unroll
        for (int nt = 0; nt < 4; nt++)
            #pragma unroll
            for (int k = 0; k < 4; k++) c[nt][k] = 0.f;

        #pragma unroll 4
        for (int ks = 0; ks < KTILE; ks += 8) {
            unsigned a[4], b[4][2];
            const int rq = wm4 + gid;
            a[0] = f2tf(sS[rq * SSR + ks + tig]);
            a[1] = f2tf(sS[(rq + 8) * SSR + ks + tig]);
            a[2] = f2tf(sS[rq * SSR + ks + tig + 4]);
            a[3] = f2tf(sS[(rq + 8) * SSR + ks + tig + 4]);
            #pragma unroll
            for (int nt = 0; nt < 4; nt++) {
                int dn = wn3 + nt * 8 + gid;
                b[nt][0] = f2tf(sVt[dn * SSR + ks + tig]);
                b[nt][1] = f2tf(sVt[dn * SSR + ks + tig + 4]);
            }
            #pragma unroll
            for (int nt = 0; nt < 4; nt++)
                mma8(c[nt], a, b[nt]);
        }
        #pragma unroll
        for (int nt = 0; nt < 4; nt++) {
            int dn = wn3 + nt * 8 + tig * 2;
            #pragma unroll
            for (int half = 0; half < 2; half++) {
                int ql = wm4 + gid + half * 8;
                int s = (q0 + ql) * 4 + r;
                *(float2*)(g_ctx + (size_t)s * DMODEL + h * DHEAD + dn) =
                    make_float2(c[nt][half * 2 + 0], c[nt][half * 2 + 1]);
            }
        }
    }
}

// ---------------- launch --------------------------------------------------------
extern "C" void kernel_launch(void* const* d_in, const int* in_sizes, int n_in,
                              void* d_out, int out_size) {
    const float* x    = (const float*)d_in[0];
    const float* beta = (const float*)d_in[1];
    const float* Wq   = (const float*)d_in[2];
    const float* bq   = (const float*)d_in[3];
    const float* Wk   = (const float*)d_in[4];
    const float* bk   = (const float*)d_in[5];
    const float* Wv   = (const float*)d_in[6];
    const float* bv   = (const float*)d_in[7];
    const float* Wo   = (const float*)d_in[8];
    const float* bo   = (const float*)d_in[9];
    float* out = (float*)d_out;

    cudaFuncSetAttribute(qkv_kernel, cudaFuncAttributeMaxDynamicSharedMemorySize,
                         GEMM_SMEM_BYTES);
    cudaFuncSetAttribute(oproj_kernel, cudaFuncAttributeMaxDynamicSharedMemorySize,
                         GEMM_SMEM_BYTES);
    cudaFuncSetAttribute(attn_kernel, cudaFuncAttributeMaxDynamicSharedMemorySize,
                         ATTN_SMEM_BYTES);

    // pack x (A-frags, mode 0) and all weights (B-frags), tf32-rounded
    pack_a_kernel<<<(SEQL * DMODEL / 4) / 256, 256>>>(x, 0);
    pack_b_kernel<<<dim3((DMODEL * DMODEL / 2) / 256, 4), 256>>>(Wq, Wk, Wv, Wo);

    qkv_kernel<<<dim3(DMODEL / 128, SEQL / 128, 3), TPB, GEMM_SMEM_BYTES>>>(
        bq, bk, bv, beta);
    attn_kernel<<<dim3(SPRIME / QTILE, 4, NHEAD), TPB, ATTN_SMEM_BYTES>>>();
    pack_a_kernel<<<(SEQL * DMODEL / 4) / 256, 256>>>(nullptr, 1);  // g_ctx -> g_packC
    oproj_kernel<<<dim3(DMODEL / 128, SEQL / 128), TPB, GEMM_SMEM_BYTES>>>(bo, out);
}

// round 13
// speedup vs baseline: 1.8208x; 1.0856x over previous
#include <cuda_runtime.h>
#include <math.h>
#include <stdint.h>

#define TPB 256
#define SEQL 3072
#define DMODEL 1024
#define NHEAD 16
#define DHEAD 64
#define SPRIME 768      // SEQL / 4 (dilation)
#define KTILE 192       // 127 + 64 key rows per attention tile
#define QTILE 64
#define KBLKS (DMODEL / 8)   // 128

// ---------------- scratch (device globals; no allocation allowed) -------------
__device__ __align__(16) float g_q[NHEAD * 4 * SPRIME * DHEAD];
__device__ __align__(16) float g_k[NHEAD * 4 * SPRIME * DHEAD];
__device__ __align__(16) float g_v[NHEAD * 4 * SPRIME * DHEAD];
__device__ __align__(16) float g_ctx[SEQL * DMODEL];
// fragment-packed operands (tf32-rounded):
__device__ __align__(16) float g_packX[SEQL * DMODEL];       // A-frag pack of x
__device__ __align__(16) float g_packC[SEQL * DMODEL];       // A-frag pack of ctx
__device__ __align__(16) float g_packW[4 * DMODEL * DMODEL]; // B-frag packs Wq,Wk,Wv,Wo

// ---------------- tf32 helpers -----------------------------------------------
__device__ __forceinline__ unsigned f2tf(float f) {
    unsigned u;
    asm("cvt.rna.tf32.f32 %0, %1;" : "=r"(u) : "f"(f));
    return u;
}

__device__ __forceinline__ void mma8(float* c, const unsigned* a, const unsigned* b) {
    asm volatile(
        "mma.sync.aligned.m16n8k8.row.col.f32.tf32.tf32.f32 "
        "{%0,%1,%2,%3}, {%4,%5,%6,%7}, {%8,%9}, {%0,%1,%2,%3};"
        : "+f"(c[0]), "+f"(c[1]), "+f"(c[2]), "+f"(c[3])
        : "r"(a[0]), "r"(a[1]), "r"(a[2]), "r"(a[3]),
          "r"(b[0]), "r"(b[1]));
}

// ---------------- cp.async helpers --------------------------------------------
__device__ __forceinline__ void cpasync16(void* s, const void* g) {
    unsigned saddr = (unsigned)__cvta_generic_to_shared(s);
    asm volatile("cp.async.cg.shared.global [%0], [%1], 16;\n" :: "r"(saddr), "l"(g));
}
__device__ __forceinline__ void cpcommit() {
    asm volatile("cp.async.commit_group;\n");
}
template<int N> __device__ __forceinline__ void cpwait() {
    asm volatile("cp.async.wait_group %0;\n" :: "n"(N));
}

// ---------------- pack kernels -------------------------------------------------
__global__ void __launch_bounds__(256) pack_a_kernel(const float* __restrict__ xsrc,
                                                     int mode) {
    const float* src = (mode == 0) ? xsrc : g_ctx;
    float* dst       = (mode == 0) ? g_packX : g_packC;
    const unsigned u = blockIdx.x * 256 + threadIdx.x;   // one float4 out
    const unsigned l = u & 31, blk = u >> 5;
    const unsigned KB = blk & (KBLKS - 1), MB = blk >> 7;
    const unsigned gid = l >> 2, tig = l & 3;
    const float* p = src + (size_t)(MB * 16 + gid) * DMODEL + KB * 8 + tig;
    uint4 o;
    o.x = f2tf(p[0]);
    o.y = f2tf(p[8 * DMODEL]);
    o.z = f2tf(p[4]);
    o.w = f2tf(p[8 * DMODEL + 4]);
    *((uint4*)dst + u) = o;
}

__global__ void __launch_bounds__(256) pack_b_kernel(
    const float* __restrict__ Wq, const float* __restrict__ Wk,
    const float* __restrict__ Wv, const float* __restrict__ Wo) {
    const int z = blockIdx.y;
    const float* W = (z == 0) ? Wq : ((z == 1) ? Wk : ((z == 2) ? Wv : Wo));
    float* dst = g_packW + (size_t)z * DMODEL * DMODEL;
    const unsigned u = blockIdx.x * 256 + threadIdx.x;   // one float2 out
    const unsigned l = u & 31, blk = u >> 5;
    const unsigned KB = blk & (KBLKS - 1), NB = blk >> 7;
    const unsigned gid = l >> 2, tig = l & 3;
    const float* p = W + (size_t)(NB * 8 + gid) * DMODEL + KB * 8 + tig;
    uint2 o;
    o.x = f2tf(p[0]);
    o.y = f2tf(p[4]);
    *((uint2*)dst + u) = o;
}

// ---------------- packed-fragment GEMM: C[128x128] -----------------------------
#define GBK 32
#define GNCH (DMODEL / GBK)                  // 32
#define CHUNK_F 4096                         // floats per operand chunk (16KB)
#define GEMM_SMEM_BYTES (4 * CHUNK_F * 4)    // 65536

__device__ __forceinline__ void gemm_body(const float* __restrict__ Ap,
                                          const float* __restrict__ Bp,
                                          int mb0, int nb0,
                                          float (&c)[2][8][4], float* sm) {
    float* sA[2] = { sm, sm + CHUNK_F };
    float* sB[2] = { sm + 2 * CHUNK_F, sm + 3 * CHUNK_F };

    const int tid  = threadIdx.x;
    const int lane = tid & 31, warp = tid >> 5;
    const int wm2 = (warp & 3) * 2;     // chunk-local mblk base
    const int wn8 = (warp >> 2) * 8;    // chunk-local nblk base

    auto stage = [&](int ch, int b) {
        const int kb0 = ch * 4;
        #pragma unroll
        for (int t = 0; t < 4; t++) {
            unsigned u = tid + t * 256;            // A 16B-unit
            unsigned i = u >> 7, j = (u >> 5) & 3, l = u & 31;
            const float* srcA = Ap + ((size_t)((mb0 + i) * KBLKS + kb0 + j) * 32 + l) * 4;
            cpasync16(sA[b] + u * 4, srcA);
        }
        #pragma unroll
        for (int t = 0; t < 4; t++) {
            unsigned u = tid + t * 256;            // B 16B-unit (2 lanes x float2)
            unsigned inb = u >> 6, rem = u & 63;
            unsigned j = rem >> 4, lp = (rem & 15) * 2;
            const float* srcB = Bp + ((size_t)((nb0 + inb) * KBLKS + kb0 + j) * 32 + lp) * 2;
            cpasync16(sB[b] + u * 4, srcB);
        }
        cpcommit();
    };

    stage(0, 0);

    for (int ch = 0; ch < GNCH; ch++) {
        const int b = ch & 1;
        if (ch + 1 < GNCH) { stage(ch + 1, b ^ 1); cpwait<1>(); }
        else               { cpwait<0>(); }
        __syncthreads();

        const float* a_s = sA[b];
        const float* b_s = sB[b];
        #pragma unroll
        for (int ks8 = 0; ks8 < 4; ks8++) {
            uint4 a[2];
            uint2 bb[8];
            #pragma unroll
            for (int mt = 0; mt < 2; mt++)
                a[mt] = *(const uint4*)(a_s + (((wm2 + mt) * 4 + ks8) * 32 + lane) * 4);
            #pragma unroll
            for (int nt = 0; nt < 8; nt++)
                bb[nt] = *(const uint2*)(b_s + (((wn8 + nt) * 4 + ks8) * 32 + lane) * 2);
            #pragma unroll
            for (int mt = 0; mt < 2; mt++)
                #pragma unroll
                for (int nt = 0; nt < 8; nt++)
                    mma8(c[mt][nt], (const unsigned*)&a[mt], (const unsigned*)&bb[nt]);
        }
        __syncthreads();
    }
}

// ---------------- QKV projection -----------------------------------------------
__global__ void __launch_bounds__(TPB, 2) qkv_kernel(
    const float* __restrict__ bq, const float* __restrict__ bk,
    const float* __restrict__ bv, const float* __restrict__ beta)
{
    extern __shared__ float sm[];
    const int z = blockIdx.z;
    const float* Bp   = g_packW + (size_t)z * DMODEL * DMODEL;
    const float* bias = (z == 0) ? bq : ((z == 1) ? bk : bv);
    float* outp       = (z == 0) ? g_q : ((z == 1) ? g_k : g_v);
    const int m0 = blockIdx.y * 128, n0 = blockIdx.x * 128;

    float c[2][8][4];
    #pragma unroll
    for (int mt = 0; mt < 2; mt++)
        #pragma unroll
        for (int nt = 0; nt < 8; nt++)
            #pragma unroll
            for (int k = 0; k < 4; k++) c[mt][nt][k] = 0.f;

    gemm_body(g_packX, Bp, m0 / 16, n0 / 8, c, sm);

    const int lane = threadIdx.x & 31, warp = threadIdx.x >> 5;
    const int wm = (warp & 3) * 32, wn = (warp >> 2) * 64;
    const int gid = lane >> 2, tig = lane & 3;

    #pragma unroll
    for (int mt = 0; mt < 2; mt++) {
        #pragma unroll
        for (int nt = 0; nt < 8; nt++) {
            int n_c = n0 + wn + nt * 8 + tig * 2;
            int h = n_c >> 6, d0 = n_c & 63;
            float sc = 1.0f;
            if (z == 0) sc = 0.125f * expf(-beta[h]);   // fold 1/(8*exp(beta)) into Q
            float b0 = bias[n_c], b1 = bias[n_c + 1];
            #pragma unroll
            for (int half = 0; half < 2; half++) {
                int s  = m0 + wm + mt * 16 + gid + half * 8;
                int rr = s & 3, sp = s >> 2;
                float v0 = (c[mt][nt][half * 2 + 0] + b0) * sc;
                float v1 = (c[mt][nt][half * 2 + 1] + b1) * sc;
                float2* dst = (float2*)(outp + (((h * 4 + rr) * SPRIME + sp) * DHEAD + d0));
                *dst = make_float2(v0, v1);
            }
        }
    }
}

// ---------------- output projection --------------------------------------------
__global__ void __launch_bounds__(TPB, 2) oproj_kernel(
    const float* __restrict__ bo, float* __restrict__ out)
{
    extern __shared__ float sm[];
    const int m0 = blockIdx.y * 128, n0 = blockIdx.x * 128;

    float c[2][8][4];
    #pragma unroll
    for (int mt = 0; mt < 2; mt++)
        #pragma unroll
        for (int nt = 0; nt < 8; nt++)
            #pragma unroll
            for (int k = 0; k < 4; k++) c[mt][nt][k] = 0.f;

    gemm_body(g_packC, g_packW + (size_t)3 * DMODEL * DMODEL, m0 / 16, n0 / 8, c, sm);

    const int lane = threadIdx.x & 31, warp = threadIdx.x >> 5;
    const int wm = (warp & 3) * 32, wn = (warp >> 2) * 64;
    const int gid = lane >> 2, tig = lane & 3;

    #pragma unroll
    for (int mt = 0; mt < 2; mt++) {
        #pragma unroll
        for (int nt = 0; nt < 8; nt++) {
            int n_c = n0 + wn + nt * 8 + tig * 2;
            float b0 = bo[n_c], b1 = bo[n_c + 1];
            #pragma unroll
            for (int half = 0; half < 2; half++) {
                int mrow = m0 + wm + mt * 16 + gid + half * 8;
                float2* dst = (float2*)(out + (size_t)mrow * DMODEL + n_c);
                *dst = make_float2(c[mt][nt][half * 2 + 0] + b0,
                                   c[mt][nt][half * 2 + 1] + b1);
            }
        }
    }
}

// ---------------- attention over dilated windows (2 CTA/SM version) ------------
// smem: sK [192][SQR=68] | sVt [64][SVR=197]; sS [64][SSR=196] ALIASES sK
// (phase ordering + barriers make the alias safe: phase1 reads sK into regs,
//  barrier, S stored over sK's storage, barrier, softmax, phase3).
// Q is preloaded per-thread from global as mma fragments (no sQ tile).
#define SQR 68
#define SVR 197
#define SSR 196
#define ATTN_SMEM_FLOATS (KTILE * SQR + 64 * SVR)       // 13056 + 12608 = 25664
#define ATTN_SMEM_BYTES (ATTN_SMEM_FLOATS * 4)          // 102656 -> 2 CTAs/SM

__global__ void __launch_bounds__(TPB, 2) attn_kernel() {
    extern __shared__ float smA[];
    float* sK  = smA;                      // [192][SQR]
    float* sVt = smA + KTILE * SQR;        // [64][SVR]
    float* sS  = smA;                      // [64][SSR] alias of sK block

    const int tid = threadIdx.x;
    const int lane = tid & 31, warp = tid >> 5;
    const int gid = lane >> 2, tig = lane & 3;
    const int qt = blockIdx.x, r = blockIdx.y, h = blockIdx.z;
    const int q0 = qt * QTILE;
    const int kbase = q0 - 127;
    const float* Qb = g_q + (h * 4 + r) * SPRIME * DHEAD;
    const float* Kb = g_k + (h * 4 + r) * SPRIME * DHEAD;
    const float* Vb = g_v + (h * 4 + r) * SPRIME * DHEAD;

    const int wm4 = (warp & 3) * 16;
    const int wn2 = (warp >> 2) * 96;
    const int rq  = wm4 + gid;

    // ---- preload Q fragments from global (issues early, overlaps staging) ----
    float qv[8][4];
    #pragma unroll
    for (int ks8 = 0; ks8 < 8; ks8++) {
        const float* qp = Qb + (q0 + rq) * DHEAD + ks8 * 8 + tig;
        qv[ks8][0] = qp[0];
        qv[ks8][1] = qp[8 * DHEAD];
        qv[ks8][2] = qp[4];
        qv[ks8][3] = qp[8 * DHEAD + 4];
    }

    // ---- stage K row-major + V transposed (zero-fill out-of-range j) ----
    #pragma unroll
    for (int i = 0; i < 12; i++) {
        int lin = tid + i * TPB;
        int rk = lin >> 4, dg = (lin & 15) * 4;
        int j = kbase + rk;
        float4 kv = make_float4(0.f, 0.f, 0.f, 0.f);
        float4 vv = make_float4(0.f, 0.f, 0.f, 0.f);
        if (j >= 0 && j < SPRIME) {
            kv = *(const float4*)(Kb + j * DHEAD + dg);
            vv = *(const float4*)(Vb + j * DHEAD + dg);
        }
        *(float4*)(sK + rk * SQR + dg) = kv;
        sVt[(dg + 0) * SVR + rk] = vv.x;
        sVt[(dg + 1) * SVR + rk] = vv.y;
        sVt[(dg + 2) * SVR + rk] = vv.z;
        sVt[(dg + 3) * SVR + rk] = vv.w;
    }
    __syncthreads();

    // ---- phase 1: S = Q.K^T via 3xTF32 (accumulators stay in regs) ----
    float c[12][4];
    #pragma unroll
    for (int nt = 0; nt < 12; nt++)
        #pragma unroll
        for (int k = 0; k < 4; k++) c[nt][k] = 0.f;

    #pragma unroll
    for (int ks8 = 0; ks8 < 8; ks8++) {
        const int ks = ks8 * 8;
        unsigned ah[4], al[4];
        #pragma unroll
        for (int j = 0; j < 4; j++) {
            ah[j] = f2tf(qv[ks8][j]);
            al[j] = f2tf(qv[ks8][j] - __uint_as_float(ah[j]));
        }
        #pragma unroll
        for (int nt = 0; nt < 12; nt++) {
            int cb = wn2 + nt * 8 + gid;
            float y0 = sK[cb * SQR + ks + tig];
            float y1 = sK[cb * SQR + ks + tig + 4];
            unsigned bh[2], bl[2];
            bh[0] = f2tf(y0); bl[0] = f2tf(y0 - __uint_as_float(bh[0]));
            bh[1] = f2tf(y1); bl[1] = f2tf(y1 - __uint_as_float(bh[1]));
            mma8(c[nt], ah, bh);
            mma8(c[nt], ah, bl);
            mma8(c[nt], al, bh);
        }
    }
    __syncthreads();     // all K reads complete before S overwrites the block

    #pragma unroll
    for (int nt = 0; nt < 12; nt++) {
        int col = wn2 + nt * 8 + tig * 2;
        *(float2*)(sS + (wm4 + gid) * SSR + col) = make_float2(c[nt][0], c[nt][1]);
        *(float2*)(sS + (wm4 + gid + 8) * SSR + col) = make_float2(c[nt][2], c[nt][3]);
    }
    __syncthreads();

    // ---- phase 2: softmax per query over its band ----
    {
        const int q = tid >> 2, sub = tid & 3;
        int lo = q;
        int lim = 127 - q0;
        if (lim > lo) lo = lim;
        const int hi = q + 127;
        float* row = sS + q * SSR;

        float mx = -3.0e38f;
        for (int rk = lo + sub; rk <= hi; rk += 4)
            mx = fmaxf(mx, row[rk]);
        mx = fmaxf(mx, __shfl_xor_sync(0xffffffffu, mx, 1));
        mx = fmaxf(mx, __shfl_xor_sync(0xffffffffu, mx, 2));

        float sum = 0.f;
        for (int rk = lo + sub; rk <= hi; rk += 4)
            sum += expf(row[rk] - mx);
        sum += __shfl_xor_sync(0xffffffffu, sum, 1);
        sum += __shfl_xor_sync(0xffffffffu, sum, 2);
        const float inv = 1.0f / sum;

        for (int rk = sub; rk < KTILE; rk += 4) {
            float p = 0.f;
            if (rk >= lo && rk <= hi)
                p = expf(row[rk] - mx) * inv;
            row[rk] = p;
        }
    }
    __syncthreads();

    // ---- phase 3: ctx = P.V via tf32 mma ----
    {
        const int wn3 = (warp >> 2) * 32;
        float cc[4][4];
        #pragma unroll
        for (int nt = 0; nt < 4; nt++)
            #pragma unroll
            for (int k = 0; k < 4; k++) cc[nt][k] = 0.f;

        #pragma unroll 4
        for (int ks = 0; ks < KTILE; ks += 8) {
            unsigned a[4], b[4][2];
            a[0] = f2tf(sS[rq * SSR + ks + tig]);
            a[1] = f2tf(sS[(rq + 8) * SSR + ks + tig]);
            a[2] = f2tf(sS[rq * SSR + ks + tig + 4]);
            a[3] = f2tf(sS[(rq + 8) * SSR + ks + tig + 4]);
            #pragma unroll
            for (int nt = 0; nt < 4; nt++) {
                int dn = wn3 + nt * 8 + gid;
                b[nt][0] = f2tf(sVt[dn * SVR + ks + tig]);
                b[nt][1] = f2tf(sVt[dn * SVR + ks + tig + 4]);
            }
            #pragma unroll
            for (int nt = 0; nt < 4; nt++)
                mma8(cc[nt], a, b[nt]);
        }
        #pragma unroll
        for (int nt = 0; nt < 4; nt++) {
            int dn = wn3 + nt * 8 + tig * 2;
            #pragma unroll
            for (int half = 0; half < 2; half++) {
                int ql = wm4 + gid + half * 8;
                int s = (q0 + ql) * 4 + r;
                *(float2*)(g_ctx + (size_t)s * DMODEL + h * DHEAD + dn) =
                    make_float2(cc[nt][half * 2 + 0], cc[nt][half * 2 + 1]);
            }
        }
    }
}

// ---------------- launch --------------------------------------------------------
extern "C" void kernel_launch(void* const* d_in, const int* in_sizes, int n_in,
                              void* d_out, int out_size) {
    const float* x    = (const float*)d_in[0];
    const float* beta = (const float*)d_in[1];
    const float* Wq   = (const float*)d_in[2];
    const float* bq   = (const float*)d_in[3];
    const float* Wk   = (const float*)d_in[4];
    const float* bk   = (const float*)d_in[5];
    const float* Wv   = (const float*)d_in[6];
    const float* bv   = (const float*)d_in[7];
    const float* Wo   = (const float*)d_in[8];
    const float* bo   = (const float*)d_in[9];
    float* out = (float*)d_out;

    cudaFuncSetAttribute(qkv_kernel, cudaFuncAttributeMaxDynamicSharedMemorySize,
                         GEMM_SMEM_BYTES);
    cudaFuncSetAttribute(oproj_kernel, cudaFuncAttributeMaxDynamicSharedMemorySize,
                         GEMM_SMEM_BYTES);
    cudaFuncSetAttribute(attn_kernel, cudaFuncAttributeMaxDynamicSharedMemorySize,
                         ATTN_SMEM_BYTES);

    // pack x (A-frags, mode 0) and all weights (B-frags), tf32-rounded
    pack_a_kernel<<<(SEQL * DMODEL / 4) / 256, 256>>>(x, 0);
    pack_b_kernel<<<dim3((DMODEL * DMODEL / 2) / 256, 4), 256>>>(Wq, Wk, Wv, Wo);

    qkv_kernel<<<dim3(DMODEL / 128, SEQL / 128, 3), TPB, GEMM_SMEM_BYTES>>>(
        bq, bk, bv, beta);
    attn_kernel<<<dim3(SPRIME / QTILE, 4, NHEAD), TPB, ATTN_SMEM_BYTES>>>();
    pack_a_kernel<<<(SEQL * DMODEL / 4) / 256, 256>>>(nullptr, 1);  // g_ctx -> g_packC
    oproj_kernel<<<dim3(DMODEL / 128, SEQL / 128), TPB, GEMM_SMEM_BYTES>>>(bo, out);
}